// round 4
// baseline (speedup 1.0000x reference)
#include <cuda_runtime.h>
#include <cuda_bf16.h>

// Problem constants
#define BATCH   16
#define HDIM    224
#define WDIM    224
#define CDIM    64
#define HO      112
#define WO      112
#define NPATCH  (HO * WO)            // 12544 per image
#define TOPK    1254

// float4-unit strides for x [B,H,W,C] NHWC
#define IMG4    (HDIM * WDIM * (CDIM / 4))   // 802816
#define ROW4    (WDIM * (CDIM / 4))          // 3584
#define PIX4    (CDIM / 4)                   // 16
#define QTR4    (IMG4 / 4)                   // 200704 (56 rows)

// Scratch (no cudaMalloc allowed)
__device__ float d_g[BATCH * NPATCH];

// Order-preserving float->uint transform (ascending uint == ascending float)
__device__ __forceinline__ unsigned f2o(float f) {
    unsigned u = __float_as_uint(f);
    return (u & 0x80000000u) ? ~u : (u | 0x80000000u);
}
__device__ __forceinline__ float o2f(unsigned u) {
    unsigned raw = (u & 0x80000000u) ? (u & 0x7fffffffu) : ~u;
    return __uint_as_float(raw);
}

// ---------------------------------------------------------------------------
// Kernel 1: gating conv (2x2, stride 2, 1 out-channel). One warp per FOUR
// horizontally-adjacent patches (8 pixels x 2 rows = 128 float4 per row pair).
// Lane l loads row-segment float4s at j = l, l+32, l+64, l+96 in each of the
// two input rows (8 loads, MLP=8). Weight float4 index for in-row position j
// is  kh*32 + (j & 31)  (since (j&31) == kw*16 + c4), so all 4 column groups
// share the same weight pair (wa=row0, wb=row1).
// ---------------------------------------------------------------------------
__global__ void __launch_bounds__(256) conv_gate_k(
        const float* __restrict__ x, const float* __restrict__ wk) {
    int b    = blockIdx.y;
    int warp = threadIdx.x >> 5;
    int lane = threadIdx.x & 31;
    int q    = blockIdx.x * 8 + warp;      // quad index in [0, 3136)
    int ho   = q / 28;                     // 28 quads per patch-row
    int wq   = q - ho * 28;                // quad column

    const float4* x4 = (const float4*)x;
    const float4* w4 = (const float4*)wk;

    int r0 = b * IMG4 + (2 * ho) * ROW4 + (8 * wq) * PIX4;
    int r1 = r0 + ROW4;

    float4 wa = __ldg(&w4[lane]);        // kh=0 weights for this lane's (kw,c4)
    float4 wb = __ldg(&w4[lane + 32]);   // kh=1

    float s[4];
    #pragma unroll
    for (int k = 0; k < 4; k++) {
        float4 a = __ldg(&x4[r0 + 32 * k + lane]);
        float4 c = __ldg(&x4[r1 + 32 * k + lane]);
        s[k] = a.x * wa.x + a.y * wa.y + a.z * wa.z + a.w * wa.w
             + c.x * wb.x + c.y * wb.y + c.z * wb.z + c.w * wb.w;
    }
    #pragma unroll
    for (int o = 16; o; o >>= 1) {
        #pragma unroll
        for (int k = 0; k < 4; k++)
            s[k] += __shfl_xor_sync(0xffffffffu, s[k], o);
    }
    if (lane == 0) {
        float4* g4 = (float4*)d_g;
        g4[(b * NPATCH) / 4 + ho * 28 + wq] = make_float4(s[0], s[1], s[2], s[3]);
    }
}

// ---------------------------------------------------------------------------
// Kernel 2: per-image radix select for the K-th largest score + in-place
// gate thresholding (fused). One block (1024 threads) per image; each thread
// keeps its ~13 transformed values in REGISTERS so the 4 MSB-first radix
// passes touch only the shared histogram. Final pass writes the gated values
// straight back to d_g (exactly TOPK nonzeros; ties claimed via shared ctr).
// ---------------------------------------------------------------------------
__global__ void __launch_bounds__(1024) selgate_k(void) {
    int b = blockIdx.x;
    float* g = d_g + b * NPATCH;
    int tid = threadIdx.x;

    // Load values into registers (transformed)
    unsigned vals[13];
    int nv = 0;
    for (int i = tid; i < NPATCH; i += 1024) vals[nv++] = f2o(g[i]);

    __shared__ unsigned hist[256];
    __shared__ unsigned s_prefix;
    __shared__ int      s_rem;
    __shared__ int      s_ctr;
    if (tid == 0) { s_prefix = 0; s_rem = TOPK; s_ctr = 0; }

    for (int shift = 24; shift >= 0; shift -= 8) {
        if (tid < 256) hist[tid] = 0;
        __syncthreads();

        unsigned prefix = s_prefix;
        unsigned hm = (shift == 24) ? 0u : ~((1u << (shift + 8)) - 1u);
        #pragma unroll
        for (int k = 0; k < 13; k++) {
            if (k < nv) {
                unsigned u = vals[k];
                if ((u & hm) == prefix)
                    atomicAdd(&hist[(u >> shift) & 255u], 1u);
            }
        }
        __syncthreads();

        if (tid == 0) {
            int rem = s_rem;
            int d = 255;
            for (; d > 0; --d) {
                if (rem > (int)hist[d]) rem -= (int)hist[d];
                else break;
            }
            s_rem = rem;
            s_prefix = prefix | ((unsigned)d << shift);
        }
        __syncthreads();
    }

    unsigned t    = s_prefix;   // exact bit pattern of K-th largest
    int      ties = s_rem;      // how many threshold-valued elems to keep

    // Fused gate write-back (no extra global reads)
    nv = 0;
    for (int i = tid; i < NPATCH; i += 1024) {
        unsigned u = vals[nv++];
        float out;
        if (u > t)       out = o2f(u);
        else if (u == t) {
            int p = atomicAdd(&s_ctr, 1);
            out = (p < ties) ? o2f(u) : 0.0f;
        } else           out = 0.0f;
        g[i] = out;
    }
}

// ---------------------------------------------------------------------------
// Kernel 3: out = x * gate_full, ILP-4. Each thread handles one float4 in
// each of the 4 image quarters (rows h, h+56, h+112, h+168 — gate row is
// (h>>1) + 28*j). 32 consecutive float4 = one gate cell, so the gate is
// warp-uniform and zero-gate cells skip the x read entirely.
// ---------------------------------------------------------------------------
__global__ void __launch_bounds__(256) apply_gate_k(
        const float* __restrict__ x, float* __restrict__ out) {
    int b     = blockIdx.y;
    int h     = blockIdx.x / 14;                       // 0..55 (quarter rows)
    int w4off = (blockIdx.x - h * 14) * 256 + threadIdx.x;  // 0..3583
    int w     = w4off >> 4;

    const float* gb = d_g + b * NPATCH;
    int gcol = w >> 1;
    int grow = h >> 1;

    float gv[4];
    #pragma unroll
    for (int j = 0; j < 4; j++)
        gv[j] = __ldg(&gb[(grow + 28 * j) * WO + gcol]);

    int i0 = b * IMG4 + h * ROW4 + w4off;
    const float4* x4 = (const float4*)x;
    float4*       o4 = (float4*)out;

    float4 r[4];
    #pragma unroll
    for (int j = 0; j < 4; j++) {
        float g = gv[j];
        if (g != 0.0f) {
            float4 v = __ldg(&x4[i0 + j * QTR4]);
            r[j] = make_float4(v.x * g, v.y * g, v.z * g, v.w * g);
        } else {
            r[j] = make_float4(0.f, 0.f, 0.f, 0.f);
        }
    }
    #pragma unroll
    for (int j = 0; j < 4; j++)
        o4[i0 + j * QTR4] = r[j];
}

// ---------------------------------------------------------------------------
extern "C" void kernel_launch(void* const* d_in, const int* in_sizes, int n_in,
                              void* d_out, int out_size) {
    const float* x  = (const float*)d_in[0];
    const float* wk = (const float*)d_in[1];
    float* out = (float*)d_out;

    // 1) conv: 4 patches per warp, 8 warps/block, gridDim.y = batch
    dim3 cgrid(392, BATCH);                 // 392*8 warps = 3136 quads/image
    conv_gate_k<<<cgrid, 256>>>(x, wk);

    // 2) fused radix select + gate threshold, one block per image
    selgate_k<<<BATCH, 1024>>>();

    // 3) apply gate, ILP-4 over image quarters
    dim3 agrid(14 * 56, BATCH);             // 784 blocks/image
    apply_gate_k<<<agrid, 256>>>(x, out);
}

// round 5
// speedup vs baseline: 1.2545x; 1.2545x over previous
#include <cuda_runtime.h>
#include <cuda_bf16.h>

// Problem constants
#define BATCH   16
#define HDIM    224
#define WDIM    224
#define CDIM    64
#define HO      112
#define WO      112
#define NPATCH  (HO * WO)            // 12544 per image
#define TOPK    1254

// float4-unit strides for x [B,H,W,C] NHWC
#define IMG4    (HDIM * WDIM * (CDIM / 4))   // 802816
#define ROW4    (WDIM * (CDIM / 4))          // 3584
#define PIX4    (CDIM / 4)                   // 16
#define QTR4    (IMG4 / 4)                   // 200704 (56 rows)

#define NBINS   4096                 // top-12-bit histogram
#define MAXCAND 4096

// Scratch (no cudaMalloc allowed)
__device__ float    d_g[BATCH * NPATCH];
__device__ unsigned d_hist[BATCH * NBINS];
__device__ unsigned d_thr[BATCH];

// Order-preserving float->uint transform (ascending uint == ascending float)
__device__ __forceinline__ unsigned f2o(float f) {
    unsigned u = __float_as_uint(f);
    return (u & 0x80000000u) ? ~u : (u | 0x80000000u);
}

// ---------------------------------------------------------------------------
// Kernel 0: zero the histograms (re-run every call for determinism)
// ---------------------------------------------------------------------------
__global__ void __launch_bounds__(1024) zero_hist_k(void) {
    d_hist[blockIdx.x * 1024 + threadIdx.x] = 0u;
}

// ---------------------------------------------------------------------------
// Kernel 1: gating conv (2x2, stride 2, 1 out-channel), 4 patches per warp,
// PLUS fused top-12-bit histogram accumulation (hidden under DRAM time).
// ---------------------------------------------------------------------------
__global__ void __launch_bounds__(256) conv_gate_k(
        const float* __restrict__ x, const float* __restrict__ wk) {
    int b    = blockIdx.y;
    int warp = threadIdx.x >> 5;
    int lane = threadIdx.x & 31;
    int q    = blockIdx.x * 8 + warp;      // quad index in [0, 3136)
    int ho   = q / 28;
    int wq   = q - ho * 28;

    const float4* x4 = (const float4*)x;
    const float4* w4 = (const float4*)wk;

    int r0 = b * IMG4 + (2 * ho) * ROW4 + (8 * wq) * PIX4;
    int r1 = r0 + ROW4;

    float4 wa = __ldg(&w4[lane]);
    float4 wb = __ldg(&w4[lane + 32]);

    float s[4];
    #pragma unroll
    for (int k = 0; k < 4; k++) {
        float4 a = __ldg(&x4[r0 + 32 * k + lane]);
        float4 c = __ldg(&x4[r1 + 32 * k + lane]);
        s[k] = a.x * wa.x + a.y * wa.y + a.z * wa.z + a.w * wa.w
             + c.x * wb.x + c.y * wb.y + c.z * wb.z + c.w * wb.w;
    }
    #pragma unroll
    for (int o = 16; o; o >>= 1) {
        #pragma unroll
        for (int k = 0; k < 4; k++)
            s[k] += __shfl_xor_sync(0xffffffffu, s[k], o);
    }
    // every lane now has the full sums; lanes 0-3 handle one score each
    if (lane < 4) {
        unsigned u = f2o(s[lane]);
        atomicAdd(&d_hist[b * NBINS + (u >> 20)], 1u);
    }
    if (lane == 0) {
        float4* g4 = (float4*)d_g;
        g4[(b * NPATCH) / 4 + ho * 28 + wq] = make_float4(s[0], s[1], s[2], s[3]);
    }
}

// ---------------------------------------------------------------------------
// Kernel 2: per-image threshold finder. One block (1024 thr) per image.
//  a) scan 4096-bin hist from the top -> 12-bit prefix + rem
//  b) gather candidates in that bin from L2-resident d_g
//  c) refine low 20 bits by counting passes -> exact K-th-largest pattern
//  d) zero out excess ties in d_g (rare), publish d_thr[b]
// ---------------------------------------------------------------------------
__global__ void __launch_bounds__(1024) findthr_k(void) {
    int b   = blockIdx.x;
    int tid = threadIdx.x;
    int lane = tid & 31, wid = tid >> 5;
    const float* g = d_g + b * NPATCH;
    const unsigned* hist = d_hist + b * NBINS;

    __shared__ unsigned partial[1024];
    __shared__ unsigned wsum[32];
    __shared__ unsigned s_pref12, s_rem, s_cnt, s_thr, s_keep, s_claim;
    __shared__ unsigned cand_u[MAXCAND];
    __shared__ unsigned short cand_i[MAXCAND];

    // a) per-thread sum of 4 bins, warp sums, then serial top-down scan
    unsigned h0 = hist[tid * 4 + 0], h1 = hist[tid * 4 + 1];
    unsigned h2 = hist[tid * 4 + 2], h3 = hist[tid * 4 + 3];
    unsigned p = h0 + h1 + h2 + h3;
    partial[tid] = p;
    unsigned ws = p;
    #pragma unroll
    for (int o = 16; o; o >>= 1) ws += __shfl_xor_sync(0xffffffffu, ws, o);
    if (lane == 0) wsum[wid] = ws;
    __syncthreads();

    if (tid == 0) {
        int rem = TOPK;
        int w = 31;
        for (; w > 0; --w) { if (rem > (int)wsum[w]) rem -= (int)wsum[w]; else break; }
        int t = w * 32 + 31;
        for (; t > w * 32; --t) { if (rem > (int)partial[t]) rem -= (int)partial[t]; else break; }
        int d = t * 4 + 3;
        for (; d > t * 4; --d) { if (rem > (int)hist[d]) rem -= (int)hist[d]; else break; }
        s_pref12 = (unsigned)d;
        s_rem = (unsigned)rem;
        s_cnt = 0;
        s_claim = 0;
    }
    __syncthreads();

    // b) gather candidates whose top-12 bits match
    unsigned pref12 = s_pref12;
    for (int i = tid; i < NPATCH; i += 1024) {
        unsigned u = f2o(g[i]);
        if ((u >> 20) == pref12) {
            unsigned pos = atomicAdd(&s_cnt, 1u);
            if (pos < MAXCAND) { cand_u[pos] = u; cand_i[pos] = (unsigned short)i; }
        }
    }
    __syncthreads();
    int cnt = min(s_cnt, (unsigned)MAXCAND);

    // c) refine the remaining 20 bits, MSB first
    if (tid == 0) s_thr = pref12 << 20;
    __syncthreads();
    __shared__ unsigned s_c;
    for (int bit = 19; bit >= 0; --bit) {
        if (tid == 0) s_c = 0;
        __syncthreads();
        unsigned want = (s_thr >> bit) | 1u;
        unsigned c = 0;
        for (int i = tid; i < cnt; i += 1024)
            c += ((cand_u[i] >> bit) == want) ? 1u : 0u;
        #pragma unroll
        for (int o = 16; o; o >>= 1) c += __shfl_xor_sync(0xffffffffu, c, o);
        if (lane == 0 && c) atomicAdd(&s_c, c);
        __syncthreads();
        if (tid == 0) {
            if (s_c >= s_rem) s_thr |= 1u << bit;
            else              s_rem -= s_c;
        }
        __syncthreads();
    }

    // d) tie cleanup: keep exactly s_rem of the thr-valued elements
    unsigned thr = s_thr, keep = s_rem;
    for (int i = tid; i < cnt; i += 1024) {
        if (cand_u[i] == thr) {
            unsigned pcl = atomicAdd(&s_claim, 1u);
            if (pcl >= keep)
                d_g[b * NPATCH + cand_i[i]] = __uint_as_float(0xFF800000u); // -inf
        }
    }
    if (tid == 0) d_thr[b] = thr;
}

// ---------------------------------------------------------------------------
// Kernel 3: out = x * gate, ILP-4 over 4 image quarters. Gate is computed
// inline from the RAW score via threshold compare (no d_g rewrite needed).
// 32 consecutive float4 = one gate cell -> warp-uniform; zero cells skip
// the x read entirely.
// ---------------------------------------------------------------------------
__global__ void __launch_bounds__(256) apply_gate_k(
        const float* __restrict__ x, float* __restrict__ out) {
    int b     = blockIdx.y;
    int h     = blockIdx.x / 14;                            // 0..55
    int w4off = (blockIdx.x - h * 14) * 256 + threadIdx.x;  // 0..3583
    int w     = w4off >> 4;

    unsigned thr = __ldg(&d_thr[b]);
    const float* gb = d_g + b * NPATCH;
    int gcol = w >> 1;
    int grow = h >> 1;

    float gv[4];
    #pragma unroll
    for (int j = 0; j < 4; j++) {
        float s = __ldg(&gb[(grow + 28 * j) * WO + gcol]);
        gv[j] = (f2o(s) >= thr) ? s : 0.0f;
    }

    int i0 = b * IMG4 + h * ROW4 + w4off;
    const float4* x4 = (const float4*)x;
    float4*       o4 = (float4*)out;

    float4 r[4];
    #pragma unroll
    for (int j = 0; j < 4; j++) {
        float gg = gv[j];
        if (gg != 0.0f) {
            float4 v = __ldg(&x4[i0 + j * QTR4]);
            r[j] = make_float4(v.x * gg, v.y * gg, v.z * gg, v.w * gg);
        } else {
            r[j] = make_float4(0.f, 0.f, 0.f, 0.f);
        }
    }
    #pragma unroll
    for (int j = 0; j < 4; j++)
        o4[i0 + j * QTR4] = r[j];
}

// ---------------------------------------------------------------------------
extern "C" void kernel_launch(void* const* d_in, const int* in_sizes, int n_in,
                              void* d_out, int out_size) {
    const float* x  = (const float*)d_in[0];
    const float* wk = (const float*)d_in[1];
    float* out = (float*)d_out;

    // 0) zero histograms (16*4096 = 65536 ints)
    zero_hist_k<<<64, 1024>>>();

    // 1) conv + fused coarse histogram
    dim3 cgrid(392, BATCH);
    conv_gate_k<<<cgrid, 256>>>(x, wk);

    // 2) per-image exact threshold from histogram + candidate refine
    findthr_k<<<BATCH, 1024>>>();

    // 3) apply gate (threshold compare inline)
    dim3 agrid(14 * 56, BATCH);
    apply_gate_k<<<agrid, 256>>>(x, out);
}

// round 8
// speedup vs baseline: 1.2662x; 1.0094x over previous
#include <cuda_runtime.h>
#include <cuda_bf16.h>

// Problem constants
#define BATCH   16
#define HDIM    224
#define WDIM    224
#define CDIM    64
#define HO      112
#define WO      112
#define NPATCH  (HO * WO)            // 12544 per image
#define TOPK    1254

// float4-unit strides for x [B,H,W,C] NHWC
#define IMG4    (HDIM * WDIM * (CDIM / 4))   // 802816
#define ROW4    (WDIM * (CDIM / 4))          // 3584
#define PIX4    (CDIM / 4)                   // 16
#define QTR4    (IMG4 / 4)                   // 200704 (56 rows)

#define NBINS   4096                 // top-12-bit histogram
#define MAXCAND 4096

// Scratch (no cudaMalloc allowed). Device globals are zero-initialized at
// module load; findthr_k re-zeroes d_hist at its end, so the hist is clean
// at the start of EVERY kernel_launch invocation (deterministic).
__device__ float    d_g[BATCH * NPATCH];
__device__ unsigned d_hist[BATCH * NBINS];
__device__ unsigned d_thr[BATCH];

// Order-preserving float->uint transform (ascending uint == ascending float)
__device__ __forceinline__ unsigned f2o(float f) {
    unsigned u = __float_as_uint(f);
    return (u & 0x80000000u) ? ~u : (u | 0x80000000u);
}

// ---------------------------------------------------------------------------
// Kernel 1: gating conv (2x2, stride 2, 1 out-channel), 4 patches per warp,
// PLUS fused top-12-bit histogram accumulation (hidden under DRAM time).
// ---------------------------------------------------------------------------
__global__ void __launch_bounds__(256) conv_gate_k(
        const float* __restrict__ x, const float* __restrict__ wk) {
    int b    = blockIdx.y;
    int warp = threadIdx.x >> 5;
    int lane = threadIdx.x & 31;
    int q    = blockIdx.x * 8 + warp;      // quad index in [0, 3136)
    int ho   = q / 28;
    int wq   = q - ho * 28;

    const float4* x4 = (const float4*)x;
    const float4* w4 = (const float4*)wk;

    int r0 = b * IMG4 + (2 * ho) * ROW4 + (8 * wq) * PIX4;
    int r1 = r0 + ROW4;

    float4 wa = __ldg(&w4[lane]);
    float4 wb = __ldg(&w4[lane + 32]);

    float s[4];
    #pragma unroll
    for (int k = 0; k < 4; k++) {
        float4 a = __ldg(&x4[r0 + 32 * k + lane]);
        float4 c = __ldg(&x4[r1 + 32 * k + lane]);
        s[k] = a.x * wa.x + a.y * wa.y + a.z * wa.z + a.w * wa.w
             + c.x * wb.x + c.y * wb.y + c.z * wb.z + c.w * wb.w;
    }
    #pragma unroll
    for (int o = 16; o; o >>= 1) {
        #pragma unroll
        for (int k = 0; k < 4; k++)
            s[k] += __shfl_xor_sync(0xffffffffu, s[k], o);
    }
    // every lane now has the full sums; lanes 0-3 handle one score each
    if (lane < 4) {
        unsigned u = f2o(s[lane]);
        atomicAdd(&d_hist[b * NBINS + (u >> 20)], 1u);
    }
    if (lane == 0) {
        float4* g4 = (float4*)d_g;
        g4[(b * NPATCH) / 4 + ho * 28 + wq] = make_float4(s[0], s[1], s[2], s[3]);
    }
}

// ---------------------------------------------------------------------------
// Kernel 2: per-image threshold finder. One block (1024 thr) per image.
//  a) scan 4096-bin hist from the top -> 12-bit prefix + rem
//  b) gather candidates in that bin from L2-resident d_g
//  c) refine low 20 bits by counting passes -> exact K-th-largest pattern
//  d) zero out excess ties in d_g (rare), publish d_thr[b]
//  e) re-zero this image's histogram for the next invocation
// ---------------------------------------------------------------------------
__global__ void __launch_bounds__(1024) findthr_k(void) {
    int b   = blockIdx.x;
    int tid = threadIdx.x;
    int lane = tid & 31, wid = tid >> 5;
    const float* g = d_g + b * NPATCH;
    const unsigned* hist = d_hist + b * NBINS;

    __shared__ unsigned partial[1024];
    __shared__ unsigned wsum[32];
    __shared__ unsigned s_pref12, s_rem, s_cnt, s_thr, s_claim;
    __shared__ unsigned cand_u[MAXCAND];
    __shared__ unsigned short cand_i[MAXCAND];

    // a) per-thread sum of 4 bins, warp sums, then serial top-down scan
    unsigned h0 = hist[tid * 4 + 0], h1 = hist[tid * 4 + 1];
    unsigned h2 = hist[tid * 4 + 2], h3 = hist[tid * 4 + 3];
    unsigned p = h0 + h1 + h2 + h3;
    partial[tid] = p;
    unsigned ws = p;
    #pragma unroll
    for (int o = 16; o; o >>= 1) ws += __shfl_xor_sync(0xffffffffu, ws, o);
    if (lane == 0) wsum[wid] = ws;
    __syncthreads();

    if (tid == 0) {
        int rem = TOPK;
        int w = 31;
        for (; w > 0; --w) { if (rem > (int)wsum[w]) rem -= (int)wsum[w]; else break; }
        int t = w * 32 + 31;
        for (; t > w * 32; --t) { if (rem > (int)partial[t]) rem -= (int)partial[t]; else break; }
        int d = t * 4 + 3;
        for (; d > t * 4; --d) { if (rem > (int)hist[d]) rem -= (int)hist[d]; else break; }
        s_pref12 = (unsigned)d;
        s_rem = (unsigned)rem;
        s_cnt = 0;
        s_claim = 0;
    }
    __syncthreads();

    // b) gather candidates whose top-12 bits match
    unsigned pref12 = s_pref12;
    for (int i = tid; i < NPATCH; i += 1024) {
        unsigned u = f2o(g[i]);
        if ((u >> 20) == pref12) {
            unsigned pos = atomicAdd(&s_cnt, 1u);
            if (pos < MAXCAND) { cand_u[pos] = u; cand_i[pos] = (unsigned short)i; }
        }
    }
    __syncthreads();
    int cnt = min(s_cnt, (unsigned)MAXCAND);

    // c) refine the remaining 20 bits, MSB first
    if (tid == 0) s_thr = pref12 << 20;
    __syncthreads();
    __shared__ unsigned s_c;
    for (int bit = 19; bit >= 0; --bit) {
        if (tid == 0) s_c = 0;
        __syncthreads();
        unsigned want = (s_thr >> bit) | 1u;
        unsigned c = 0;
        for (int i = tid; i < cnt; i += 1024)
            c += ((cand_u[i] >> bit) == want) ? 1u : 0u;
        #pragma unroll
        for (int o = 16; o; o >>= 1) c += __shfl_xor_sync(0xffffffffu, c, o);
        if (lane == 0 && c) atomicAdd(&s_c, c);
        __syncthreads();
        if (tid == 0) {
            if (s_c >= s_rem) s_thr |= 1u << bit;
            else              s_rem -= s_c;
        }
        __syncthreads();
    }

    // d) tie cleanup: keep exactly s_rem of the thr-valued elements
    unsigned thr = s_thr, keep = s_rem;
    for (int i = tid; i < cnt; i += 1024) {
        if (cand_u[i] == thr) {
            unsigned pcl = atomicAdd(&s_claim, 1u);
            if (pcl >= keep)
                d_g[b * NPATCH + cand_i[i]] = __uint_as_float(0xFF800000u); // -inf
        }
    }
    if (tid == 0) d_thr[b] = thr;

    // e) re-zero this image's histogram bins for the next invocation
    __syncthreads();
    #pragma unroll
    for (int i = 0; i < NBINS / 1024; i++)
        d_hist[b * NBINS + i * 1024 + tid] = 0u;
}

// ---------------------------------------------------------------------------
// Kernel 3: out = x * gate, ILP-8: two w-segments x 4 image quarters per
// thread. Gate computed inline from the RAW score via threshold compare.
// 32 consecutive float4 = one gate cell -> warp-uniform; zero cells skip
// the x read. Streaming stores (evict-first) for the never-re-read output.
// ---------------------------------------------------------------------------
__global__ void __launch_bounds__(256) apply_gate_k(
        const float* __restrict__ x, float* __restrict__ out) {
    int b   = blockIdx.y;
    int h   = blockIdx.x / 7;                       // 0..55 (quarter rows)
    int seg = blockIdx.x - h * 7;                   // 0..6
    int w0  = seg * 512 + threadIdx.x;              // first float4 col
    int w1  = w0 + 256;                             // second float4 col

    unsigned thr = __ldg(&d_thr[b]);
    const float* gb = d_g + b * NPATCH;
    int grow  = h >> 1;
    int gcol0 = w0 >> 5;                            // (w0>>4)>>1
    int gcol1 = w1 >> 5;

    float gv[8];
    #pragma unroll
    for (int j = 0; j < 4; j++) {
        int gr = (grow + 28 * j) * WO;
        float s0 = __ldg(&gb[gr + gcol0]);
        float s1 = __ldg(&gb[gr + gcol1]);
        gv[j]     = (f2o(s0) >= thr) ? s0 : 0.0f;
        gv[j + 4] = (f2o(s1) >= thr) ? s1 : 0.0f;
    }

    int i0 = b * IMG4 + h * ROW4;
    const float4* x4 = (const float4*)x;
    float4*       o4 = (float4*)out;

    float4 r[8];
    #pragma unroll
    for (int j = 0; j < 4; j++) {
        float g0 = gv[j], g1 = gv[j + 4];
        int base = i0 + j * QTR4;
        if (g0 != 0.0f) {
            float4 v = __ldg(&x4[base + w0]);
            r[j] = make_float4(v.x * g0, v.y * g0, v.z * g0, v.w * g0);
        } else r[j] = make_float4(0.f, 0.f, 0.f, 0.f);
        if (g1 != 0.0f) {
            float4 v = __ldg(&x4[base + w1]);
            r[j + 4] = make_float4(v.x * g1, v.y * g1, v.z * g1, v.w * g1);
        } else r[j + 4] = make_float4(0.f, 0.f, 0.f, 0.f);
    }
    #pragma unroll
    for (int j = 0; j < 4; j++) {
        int base = i0 + j * QTR4;
        __stcs(&o4[base + w0], r[j]);
        __stcs(&o4[base + w1], r[j + 4]);
    }
}

// ---------------------------------------------------------------------------
extern "C" void kernel_launch(void* const* d_in, const int* in_sizes, int n_in,
                              void* d_out, int out_size) {
    const float* x  = (const float*)d_in[0];
    const float* wk = (const float*)d_in[1];
    float* out = (float*)d_out;

    // 1) conv + fused coarse histogram (hist arrives zeroed — see d_hist note)
    dim3 cgrid(392, BATCH);
    conv_gate_k<<<cgrid, 256>>>(x, wk);

    // 2) per-image exact threshold from histogram + candidate refine
    //    (also re-zeroes the histogram for the next invocation)
    findthr_k<<<BATCH, 1024>>>();

    // 3) apply gate, ILP-8, streaming stores
    dim3 agrid(7 * 56, BATCH);
    apply_gate_k<<<agrid, 256>>>(x, out);
}